// round 1
// baseline (speedup 1.0000x reference)
#include <cuda_runtime.h>

// CapsuleLayer dynamic routing, fused single kernel.
// x: [B=64, Cin=8, R=800] fp32
// W: [NC=128, R=800, Cin=8, O=16] fp32
// out: [B=64, O=16, NC=128] fp32,  out[b,o,c] = squash-routed outputs[c,b,o]
//
// One CTA per (capsule c, group of G=2 batch items). priors live entirely in
// shared memory; W[c] is streamed once per CTA (each element reused for both
// b's in registers). Consecutive blockIdx share c -> W[c] stays L2-resident.

namespace {

constexpr int kB   = 64;
constexpr int kCin = 8;
constexpr int kR   = 800;
constexpr int kNC  = 128;
constexpr int kO   = 16;
constexpr int kG   = 2;            // batch items per CTA
constexpr int kT   = 512;          // threads per CTA
constexpr int kBPC = kB / kG;      // 32 blocks per capsule
constexpr int kIters = 3;

struct Smem {
    float prio[kG][kO][kR];     // 102400 B  (o-major: conflict-free for both access patterns)
    float xs[kG][kCin][kR];     //  51200 B
    float logits[kG][kR];       //   6400 B
    float probs[kG][kR];        //   6400 B  (unnormalized exp; 1/Z folded into next s-pass)
    float v[kG][kO];            //    128 B
    float red[kG][32];          //    256 B  (warp partials / s-vector staging)
    float bc[kG][4];            //     32 B  ([0]=max logit, [1]=1/Z)
};

} // namespace

__global__ __launch_bounds__(kT, 1)
void caps_route_kernel(const float* __restrict__ x,
                       const float* __restrict__ W,
                       float* __restrict__ out) {
    extern __shared__ char smem_raw[];
    Smem* S = reinterpret_cast<Smem*>(smem_raw);

    const int t  = threadIdx.x;
    const int c  = blockIdx.x / kBPC;
    const int b0 = (blockIdx.x % kBPC) * kG;
    const float* Wc = W + (size_t)c * (kR * kCin * kO);

    // ------- stage x slices into smem; zero logits -------
    #pragma unroll
    for (int g = 0; g < kG; g++) {
        const float4* src = reinterpret_cast<const float4*>(x + (size_t)(b0 + g) * (kCin * kR));
        float4* dst = reinterpret_cast<float4*>(&S->xs[g][0][0]);
        for (int i = t; i < (kCin * kR) / 4; i += kT) dst[i] = src[i];
    }
    for (int i = t; i < kG * kR; i += kT) (&S->logits[0][0])[i] = 0.f;
    __syncthreads();

    // ------- phase 1: priors[g][o][r] = sum_i x[b,i,r] * W[c,r,i,o] -------
    // Thread quad (o4 = t&3) handles 4 o's of one r; W row loaded once into
    // registers and reused for both g (this is what halves the L2 traffic).
    {
        const int o4 = t & 3;
        for (int r = t >> 2; r < kR; r += (kT >> 2)) {
            const float4* wrow =
                reinterpret_cast<const float4*>(Wc + (size_t)r * (kCin * kO)) + o4;
            float4 w[kCin];
            #pragma unroll
            for (int i = 0; i < kCin; i++) w[i] = wrow[i * 4];
            #pragma unroll
            for (int g = 0; g < kG; g++) {
                float4 acc = make_float4(0.f, 0.f, 0.f, 0.f);
                #pragma unroll
                for (int i = 0; i < kCin; i++) {
                    const float xv = S->xs[g][i][r];
                    acc.x = fmaf(xv, w[i].x, acc.x);
                    acc.y = fmaf(xv, w[i].y, acc.y);
                    acc.z = fmaf(xv, w[i].z, acc.z);
                    acc.w = fmaf(xv, w[i].w, acc.w);
                }
                S->prio[g][o4 * 4 + 0][r] = acc.x;
                S->prio[g][o4 * 4 + 1][r] = acc.y;
                S->prio[g][o4 * 4 + 2][r] = acc.z;
                S->prio[g][o4 * 4 + 3][r] = acc.w;
            }
        }
    }
    __syncthreads();

    // ------- phase 2: routing (all in smem) -------
    const int warp = t >> 5;
    const int lane = t & 31;

    for (int it = 0; it < kIters; it++) {
        // s[g][o] = (1/Z) * sum_r probs[r] * prio[g][o][r]
        // 32 columns (g,o), 16 threads each, float4 over r.
        {
            const int col = t >> 4;        // 0..31
            const int gq  = col >> 4;      // 0..kG-1
            const int o   = col & 15;
            const int sub = t & 15;
            const float4* prow = reinterpret_cast<const float4*>(&S->prio[gq][o][0]);
            float acc = 0.f;
            if (it == 0) {                 // softmax(0) == uniform 1/R
                for (int r4 = sub; r4 < kR / 4; r4 += 16) {
                    const float4 p = prow[r4];
                    acc += (p.x + p.y) + (p.z + p.w);
                }
                acc *= (1.f / kR);
            } else {
                const float4* qrow = reinterpret_cast<const float4*>(&S->probs[gq][0]);
                for (int r4 = sub; r4 < kR / 4; r4 += 16) {
                    const float4 p = prow[r4];
                    const float4 q = qrow[r4];
                    acc += p.x * q.x + p.y * q.y + p.z * q.z + p.w * q.w;
                }
                acc *= S->bc[gq][1];       // 1/Z from previous iteration
            }
            #pragma unroll
            for (int off = 8; off; off >>= 1)
                acc += __shfl_xor_sync(0xffffffffu, acc, off);
            if (sub == 0) S->red[gq][o] = acc;
        }
        __syncthreads();

        // squash; last iteration writes output directly
        if (warp < kG && lane < 16) {
            const float sv = S->red[warp][lane];
            float sq = sv * sv;
            #pragma unroll
            for (int off = 8; off; off >>= 1)
                sq += __shfl_xor_sync(0x0000ffffu, sq, off);
            const float coef = sqrtf(sq) / (1.f + sq);   // sn/((1+sn)*sqrt(sn))
            const float vv = sv * coef;
            if (it < kIters - 1) S->v[warp][lane] = vv;
            else out[(size_t)(b0 + warp) * (kO * kNC) + (size_t)lane * kNC + c] = vv;
        }
        if (it == kIters - 1) return;
        __syncthreads();

        // delta[r] = sum_o prio[g][o][r] * v[g][o]; logits += delta; track max
        #pragma unroll
        for (int gg = 0; gg < kG; gg++) {
            float lmax = -1e30f;
            for (int r = t; r < kR; r += kT) {
                float d = 0.f;
                #pragma unroll
                for (int o2 = 0; o2 < kO; o2++)
                    d = fmaf(S->prio[gg][o2][r], S->v[gg][o2], d);
                const float lg = S->logits[gg][r] + d;
                S->logits[gg][r] = lg;
                lmax = fmaxf(lmax, lg);
            }
            #pragma unroll
            for (int off = 16; off; off >>= 1)
                lmax = fmaxf(lmax, __shfl_xor_sync(0xffffffffu, lmax, off));
            if (lane == 0) S->red[gg][warp] = lmax;
        }
        __syncthreads();
        if (warp < kG && lane < 16) {
            float m = S->red[warp][lane];
            #pragma unroll
            for (int off = 8; off; off >>= 1)
                m = fmaxf(m, __shfl_xor_sync(0x0000ffffu, m, off));
            if (lane == 0) S->bc[warp][0] = m;
        }
        __syncthreads();

        // probs[r] = exp(logits[r] - max); Z reduced; keep unnormalized + 1/Z
        #pragma unroll
        for (int gg = 0; gg < kG; gg++) {
            const float cm = S->bc[gg][0];
            float es = 0.f;
            for (int r = t; r < kR; r += kT) {
                const float e = __expf(S->logits[gg][r] - cm);
                S->probs[gg][r] = e;
                es += e;
            }
            #pragma unroll
            for (int off = 16; off; off >>= 1)
                es += __shfl_xor_sync(0xffffffffu, es, off);
            if (lane == 0) S->red[gg][warp] = es;
        }
        __syncthreads();
        if (warp < kG && lane < 16) {
            float z = S->red[warp][lane];
            #pragma unroll
            for (int off = 8; off; off >>= 1)
                z += __shfl_xor_sync(0x0000ffffu, z, off);
            if (lane == 0) S->bc[warp][1] = 1.f / z;
        }
        __syncthreads();
    }
}

extern "C" void kernel_launch(void* const* d_in, const int* in_sizes, int n_in,
                              void* d_out, int out_size) {
    const float* x = (const float*)d_in[0];            // [64, 8, 800]
    const float* W = (const float*)d_in[1];            // [128, 800, 8, 16]
    float* out = (float*)d_out;                        // [64, 16, 128]

    static_assert(sizeof(Smem) <= 227 * 1024, "smem budget");
    cudaFuncSetAttribute(caps_route_kernel,
                         cudaFuncAttributeMaxDynamicSharedMemorySize,
                         (int)sizeof(Smem));
    caps_route_kernel<<<kNC * kBPC, kT, sizeof(Smem)>>>(x, W, out);
}

// round 2
// speedup vs baseline: 1.0058x; 1.0058x over previous
#include <cuda_runtime.h>

// CapsuleLayer dynamic routing, fused single kernel.
// x: [B=64, Cin=8, R=800] fp32
// W: [NC=128, R=800, Cin=8, O=16] fp32
// out: [B=64, O=16, NC=128] fp32,  out[b,o,c] = squash-routed outputs[c,b,o]
//
// One CTA per (capsule c, group of G=2 batch items). priors live entirely in
// shared memory; W[c] is streamed once per CTA (each element reused for both
// b's in registers). Consecutive blockIdx share c -> W[c] stays L2-resident.

namespace {

constexpr int kB   = 64;
constexpr int kCin = 8;
constexpr int kR   = 800;
constexpr int kNC  = 128;
constexpr int kO   = 16;
constexpr int kG   = 2;            // batch items per CTA
constexpr int kT   = 512;          // threads per CTA
constexpr int kBPC = kB / kG;      // 32 blocks per capsule
constexpr int kIters = 3;

struct Smem {
    float prio[kG][kO][kR];     // 102400 B  (o-major: conflict-free for both access patterns)
    float xs[kG][kCin][kR];     //  51200 B
    float logits[kG][kR];       //   6400 B
    float probs[kG][kR];        //   6400 B  (unnormalized exp; 1/Z folded into next s-pass)
    float v[kG][kO];            //    128 B
    float red[kG][32];          //    256 B  (warp partials / s-vector staging)
    float bc[kG][4];            //     32 B  ([0]=max logit, [1]=1/Z)
};

} // namespace

__global__ __launch_bounds__(kT, 1)
void caps_route_kernel(const float* __restrict__ x,
                       const float* __restrict__ W,
                       float* __restrict__ out) {
    extern __shared__ char smem_raw[];
    Smem* S = reinterpret_cast<Smem*>(smem_raw);

    const int t  = threadIdx.x;
    const int c  = blockIdx.x / kBPC;
    const int b0 = (blockIdx.x % kBPC) * kG;
    const float* Wc = W + (size_t)c * (kR * kCin * kO);

    // ------- stage x slices into smem; zero logits -------
    #pragma unroll
    for (int g = 0; g < kG; g++) {
        const float4* src = reinterpret_cast<const float4*>(x + (size_t)(b0 + g) * (kCin * kR));
        float4* dst = reinterpret_cast<float4*>(&S->xs[g][0][0]);
        for (int i = t; i < (kCin * kR) / 4; i += kT) dst[i] = src[i];
    }
    for (int i = t; i < kG * kR; i += kT) (&S->logits[0][0])[i] = 0.f;
    __syncthreads();

    // ------- phase 1: priors[g][o][r] = sum_i x[b,i,r] * W[c,r,i,o] -------
    // Thread quad (o4 = t&3) handles 4 o's of one r; W row loaded once into
    // registers and reused for both g (this is what halves the L2 traffic).
    {
        const int o4 = t & 3;
        for (int r = t >> 2; r < kR; r += (kT >> 2)) {
            const float4* wrow =
                reinterpret_cast<const float4*>(Wc + (size_t)r * (kCin * kO)) + o4;
            float4 w[kCin];
            #pragma unroll
            for (int i = 0; i < kCin; i++) w[i] = wrow[i * 4];
            #pragma unroll
            for (int g = 0; g < kG; g++) {
                float4 acc = make_float4(0.f, 0.f, 0.f, 0.f);
                #pragma unroll
                for (int i = 0; i < kCin; i++) {
                    const float xv = S->xs[g][i][r];
                    acc.x = fmaf(xv, w[i].x, acc.x);
                    acc.y = fmaf(xv, w[i].y, acc.y);
                    acc.z = fmaf(xv, w[i].z, acc.z);
                    acc.w = fmaf(xv, w[i].w, acc.w);
                }
                S->prio[g][o4 * 4 + 0][r] = acc.x;
                S->prio[g][o4 * 4 + 1][r] = acc.y;
                S->prio[g][o4 * 4 + 2][r] = acc.z;
                S->prio[g][o4 * 4 + 3][r] = acc.w;
            }
        }
    }
    __syncthreads();

    // ------- phase 2: routing (all in smem) -------
    const int warp = t >> 5;
    const int lane = t & 31;

    for (int it = 0; it < kIters; it++) {
        // s[g][o] = (1/Z) * sum_r probs[r] * prio[g][o][r]
        // 32 columns (g,o), 16 threads each, float4 over r.
        {
            const int col = t >> 4;        // 0..31
            const int gq  = col >> 4;      // 0..kG-1
            const int o   = col & 15;
            const int sub = t & 15;
            const float4* prow = reinterpret_cast<const float4*>(&S->prio[gq][o][0]);
            float acc = 0.f;
            if (it == 0) {                 // softmax(0) == uniform 1/R
                for (int r4 = sub; r4 < kR / 4; r4 += 16) {
                    const float4 p = prow[r4];
                    acc += (p.x + p.y) + (p.z + p.w);
                }
                acc *= (1.f / kR);
            } else {
                const float4* qrow = reinterpret_cast<const float4*>(&S->probs[gq][0]);
                for (int r4 = sub; r4 < kR / 4; r4 += 16) {
                    const float4 p = prow[r4];
                    const float4 q = qrow[r4];
                    acc += p.x * q.x + p.y * q.y + p.z * q.z + p.w * q.w;
                }
                acc *= S->bc[gq][1];       // 1/Z from previous iteration
            }
            #pragma unroll
            for (int off = 8; off; off >>= 1)
                acc += __shfl_xor_sync(0xffffffffu, acc, off);
            if (sub == 0) S->red[gq][o] = acc;
        }
        __syncthreads();

        // squash; last iteration writes output directly
        if (warp < kG && lane < 16) {
            const float sv = S->red[warp][lane];
            float sq = sv * sv;
            #pragma unroll
            for (int off = 8; off; off >>= 1)
                sq += __shfl_xor_sync(0x0000ffffu, sq, off);
            const float coef = sqrtf(sq) / (1.f + sq);   // sn/((1+sn)*sqrt(sn))
            const float vv = sv * coef;
            if (it < kIters - 1) S->v[warp][lane] = vv;
            else out[(size_t)(b0 + warp) * (kO * kNC) + (size_t)lane * kNC + c] = vv;
        }
        if (it == kIters - 1) return;
        __syncthreads();

        // delta[r] = sum_o prio[g][o][r] * v[g][o]; logits += delta; track max
        #pragma unroll
        for (int gg = 0; gg < kG; gg++) {
            float lmax = -1e30f;
            for (int r = t; r < kR; r += kT) {
                float d = 0.f;
                #pragma unroll
                for (int o2 = 0; o2 < kO; o2++)
                    d = fmaf(S->prio[gg][o2][r], S->v[gg][o2], d);
                const float lg = S->logits[gg][r] + d;
                S->logits[gg][r] = lg;
                lmax = fmaxf(lmax, lg);
            }
            #pragma unroll
            for (int off = 16; off; off >>= 1)
                lmax = fmaxf(lmax, __shfl_xor_sync(0xffffffffu, lmax, off));
            if (lane == 0) S->red[gg][warp] = lmax;
        }
        __syncthreads();
        if (warp < kG && lane < 16) {
            float m = S->red[warp][lane];
            #pragma unroll
            for (int off = 8; off; off >>= 1)
                m = fmaxf(m, __shfl_xor_sync(0x0000ffffu, m, off));
            if (lane == 0) S->bc[warp][0] = m;
        }
        __syncthreads();

        // probs[r] = exp(logits[r] - max); Z reduced; keep unnormalized + 1/Z
        #pragma unroll
        for (int gg = 0; gg < kG; gg++) {
            const float cm = S->bc[gg][0];
            float es = 0.f;
            for (int r = t; r < kR; r += kT) {
                const float e = __expf(S->logits[gg][r] - cm);
                S->probs[gg][r] = e;
                es += e;
            }
            #pragma unroll
            for (int off = 16; off; off >>= 1)
                es += __shfl_xor_sync(0xffffffffu, es, off);
            if (lane == 0) S->red[gg][warp] = es;
        }
        __syncthreads();
        if (warp < kG && lane < 16) {
            float z = S->red[warp][lane];
            #pragma unroll
            for (int off = 8; off; off >>= 1)
                z += __shfl_xor_sync(0x0000ffffu, z, off);
            if (lane == 0) S->bc[warp][1] = 1.f / z;
        }
        __syncthreads();
    }
}

extern "C" void kernel_launch(void* const* d_in, const int* in_sizes, int n_in,
                              void* d_out, int out_size) {
    const float* x = (const float*)d_in[0];            // [64, 8, 800]
    const float* W = (const float*)d_in[1];            // [128, 800, 8, 16]
    float* out = (float*)d_out;                        // [64, 16, 128]

    static_assert(sizeof(Smem) <= 227 * 1024, "smem budget");
    cudaFuncSetAttribute(caps_route_kernel,
                         cudaFuncAttributeMaxDynamicSharedMemorySize,
                         (int)sizeof(Smem));
    caps_route_kernel<<<kNC * kBPC, kT, sizeof(Smem)>>>(x, W, out);
}

// round 3
// speedup vs baseline: 1.3323x; 1.3246x over previous
#include <cuda_runtime.h>
#include <cuda_fp16.h>

// CapsuleLayer dynamic routing, fused single kernel, round 2.
// x: [B=64, Cin=8, R=800] fp32
// W: [NC=128, R=800, Cin=8, O=16] fp32
// out: [B=64, O=16, NC=128] fp32
//
// One CTA per (capsule c, 2 batch items). priors kept in smem as fp16,
// r-major rows (16 halves = 32B) so every phase-2 pass is a dense,
// coalesced row read. W streamed with whole-128B-line LDGs. probs array
// eliminated (online max/Z in the delta pass, exp recomputed in s-pass).
// 2 CTAs/SM.

namespace {

constexpr int kB    = 64;
constexpr int kCin  = 8;
constexpr int kR    = 800;
constexpr int kNC   = 128;
constexpr int kO    = 16;
constexpr int kG    = 2;
constexpr int kT    = 512;
constexpr int kBPC  = kB / kG;        // 32 CTAs per capsule
constexpr int kIters = 3;
constexpr int kWRow = kCin * kO;      // 128 floats per W r-row

struct Smem {
    __half2 prio[kG][kR][kO / 2];     // 51200 B, row = 32B
    float   xs[kG][kCin][kR];         // 51200 B
    float   logits[kG][kR];           //  6400 B
    float   sred[kG][16][kO];         //  2048 B  (per-warp s partials)
    float   mzred[kG][16][2];         //   256 B  (per-warp online m,z)
    float   v[kG][kO];                //   128 B
    float   scal[kG][2];              //    16 B  (m, 1/Z)
};

} // namespace

__global__ __launch_bounds__(kT, 2)
void caps_route_kernel(const float* __restrict__ x,
                       const float* __restrict__ W,
                       float* __restrict__ out) {
    extern __shared__ char smem_raw[];
    Smem* S = reinterpret_cast<Smem*>(smem_raw);

    const int t    = threadIdx.x;
    const int lane = t & 31;
    const int warp = t >> 5;
    const int c    = blockIdx.x / kBPC;
    const int b0   = (blockIdx.x % kBPC) * kG;
    const float* Wc = W + (size_t)c * (kR * kWRow);

    // ---- stage x slices (fp32) ----
    #pragma unroll
    for (int g = 0; g < kG; g++) {
        const float4* src = reinterpret_cast<const float4*>(x + (size_t)(b0 + g) * (kCin * kR));
        float4* dst = reinterpret_cast<float4*>(&S->xs[g][0][0]);
        for (int i = t; i < (kCin * kR) / 4; i += kT) dst[i] = src[i];
    }
    __syncthreads();

    // ---- phase 1: priors[g][r][o] = sum_i x[g][i][r] * W[c,r,i,o] ----
    // lane = (rr:2 | lo3:3). Each LDG.128 covers 4 whole 128B lines.
    // Thread's float4 = W[r, i, o0..o0+3], i = ch*2 + (lo3>>2), o0 = (lo3&3)*4.
    {
        const int lo3   = lane & 7;
        const int rr    = lane >> 3;
        const int ihalf = lo3 >> 2;
        const int oq    = lo3 & 3;
        for (int gi = warp; gi < kR / 4; gi += kT / 32) {
            const int r = gi * 4 + rr;
            float xv0[4], xv1[4];
            #pragma unroll
            for (int k = 0; k < 4; k++) {
                xv0[k] = S->xs[0][2 * k + ihalf][r];
                xv1[k] = S->xs[1][2 * k + ihalf][r];
            }
            const float4* wr = reinterpret_cast<const float4*>(Wc + (size_t)r * kWRow) + lo3;
            float4 a0 = make_float4(0.f, 0.f, 0.f, 0.f);
            float4 a1 = make_float4(0.f, 0.f, 0.f, 0.f);
            #pragma unroll
            for (int ch = 0; ch < 4; ch++) {
                const float4 w = __ldg(wr + ch * 8);   // +128B per chunk
                a0.x = fmaf(w.x, xv0[ch], a0.x);
                a0.y = fmaf(w.y, xv0[ch], a0.y);
                a0.z = fmaf(w.z, xv0[ch], a0.z);
                a0.w = fmaf(w.w, xv0[ch], a0.w);
                a1.x = fmaf(w.x, xv1[ch], a1.x);
                a1.y = fmaf(w.y, xv1[ch], a1.y);
                a1.z = fmaf(w.z, xv1[ch], a1.z);
                a1.w = fmaf(w.w, xv1[ch], a1.w);
            }
            // combine the two i-halves (partner = lane ^ 4)
            a0.x += __shfl_xor_sync(0xffffffffu, a0.x, 4);
            a0.y += __shfl_xor_sync(0xffffffffu, a0.y, 4);
            a0.z += __shfl_xor_sync(0xffffffffu, a0.z, 4);
            a0.w += __shfl_xor_sync(0xffffffffu, a0.w, 4);
            a1.x += __shfl_xor_sync(0xffffffffu, a1.x, 4);
            a1.y += __shfl_xor_sync(0xffffffffu, a1.y, 4);
            a1.z += __shfl_xor_sync(0xffffffffu, a1.z, 4);
            a1.w += __shfl_xor_sync(0xffffffffu, a1.w, 4);
            if (ihalf == 0) {
                union { __half2 h[2]; uint2 u; } cv;
                cv.h[0] = __floats2half2_rn(a0.x, a0.y);
                cv.h[1] = __floats2half2_rn(a0.z, a0.w);
                *reinterpret_cast<uint2*>(&S->prio[0][r][oq * 2]) = cv.u;
                cv.h[0] = __floats2half2_rn(a1.x, a1.y);
                cv.h[1] = __floats2half2_rn(a1.z, a1.w);
                *reinterpret_cast<uint2*>(&S->prio[1][r][oq * 2]) = cv.u;
            }
        }
    }
    __syncthreads();

    // ---- phase 2: routing ----
    // thread = (r-slot: t>>1, o-half: t&1). Row reads are dense uint4 LDS.
    const int ho = t & 1;

    for (int it = 0; it < kIters; it++) {
        // -- pass A: s[g][o] = sum_r probs[g][r] * prio[g][r][o] --
        {
            float sa[kG][8];
            #pragma unroll
            for (int g = 0; g < kG; g++)
                #pragma unroll
                for (int j = 0; j < 8; j++) sa[g][j] = 0.f;

            float m0 = 0.f, iz0 = 0.f, m1 = 0.f, iz1 = 0.f;
            if (it > 0) {
                m0 = S->scal[0][0]; iz0 = S->scal[0][1];
                m1 = S->scal[1][0]; iz1 = S->scal[1][1];
            }
            for (int r = t >> 1; r < kR; r += kT / 2) {
                #pragma unroll
                for (int g = 0; g < kG; g++) {
                    float wgt;
                    if (it == 0) wgt = 1.f / kR;
                    else {
                        const float m  = (g == 0) ? m0 : m1;
                        const float iz = (g == 0) ? iz0 : iz1;
                        wgt = __expf(S->logits[g][r] - m) * iz;
                    }
                    const __half2* row = &S->prio[g][r][ho * 4];
                    #pragma unroll
                    for (int j = 0; j < 4; j++) {
                        const float2 p = __half22float2(row[j]);
                        sa[g][2 * j]     = fmaf(wgt, p.x, sa[g][2 * j]);
                        sa[g][2 * j + 1] = fmaf(wgt, p.y, sa[g][2 * j + 1]);
                    }
                }
            }
            // reduce over lanes with equal parity (strides 16,8,4,2)
            #pragma unroll
            for (int s = 16; s >= 2; s >>= 1) {
                #pragma unroll
                for (int g = 0; g < kG; g++)
                    #pragma unroll
                    for (int j = 0; j < 8; j++)
                        sa[g][j] += __shfl_xor_sync(0xffffffffu, sa[g][j], s);
            }
            if (lane < 2) {
                #pragma unroll
                for (int g = 0; g < kG; g++)
                    #pragma unroll
                    for (int j = 0; j < 8; j++)
                        S->sred[g][warp][lane * 8 + j] = sa[g][j];
            }
        }
        __syncthreads();

        // -- finalize s, squash; last iteration writes output --
        if (warp < kG && lane < 16) {
            float s = 0.f;
            #pragma unroll
            for (int w = 0; w < 16; w++) s += S->sred[warp][w][lane];
            float sq = s * s;
            #pragma unroll
            for (int off = 8; off; off >>= 1)
                sq += __shfl_xor_sync(0x0000ffffu, sq, off);
            const float coef = sqrtf(sq) / (1.f + sq);
            const float vv = s * coef;
            if (it < kIters - 1) S->v[warp][lane] = vv;
            else out[(size_t)(b0 + warp) * (kO * kNC) + (size_t)lane * kNC + c] = vv;
        }
        if (it == kIters - 1) return;
        __syncthreads();

        // -- pass B: delta + logits update + online (m, z) per g --
        {
            float vv[kG][8];
            #pragma unroll
            for (int g = 0; g < kG; g++)
                #pragma unroll
                for (int j = 0; j < 8; j++) vv[g][j] = S->v[g][ho * 8 + j];

            float mg[kG], zg[kG];
            #pragma unroll
            for (int g = 0; g < kG; g++) { mg[g] = -1e30f; zg[g] = 0.f; }

            for (int r = t >> 1; r < kR; r += kT / 2) {
                #pragma unroll
                for (int g = 0; g < kG; g++) {
                    const __half2* row = &S->prio[g][r][ho * 4];
                    float dh = 0.f;
                    #pragma unroll
                    for (int j = 0; j < 4; j++) {
                        const float2 p = __half22float2(row[j]);
                        dh = fmaf(p.x, vv[g][2 * j], dh);
                        dh = fmaf(p.y, vv[g][2 * j + 1], dh);
                    }
                    const float d = dh + __shfl_xor_sync(0xffffffffu, dh, 1);
                    if (ho == 0) {
                        const float lg = (it == 0 ? 0.f : S->logits[g][r]) + d;
                        S->logits[g][r] = lg;
                        const float nm = fmaxf(mg[g], lg);
                        zg[g] = zg[g] * __expf(mg[g] - nm) + __expf(lg - nm);
                        mg[g] = nm;
                    }
                }
            }
            // warp-level online merge (odd lanes are neutral: m=-1e30, z=0)
            #pragma unroll
            for (int s = 16; s >= 1; s >>= 1) {
                #pragma unroll
                for (int g = 0; g < kG; g++) {
                    const float om = __shfl_xor_sync(0xffffffffu, mg[g], s);
                    const float oz = __shfl_xor_sync(0xffffffffu, zg[g], s);
                    const float nm = fmaxf(mg[g], om);
                    zg[g] = zg[g] * __expf(mg[g] - nm) + oz * __expf(om - nm);
                    mg[g] = nm;
                }
            }
            if (lane == 0) {
                #pragma unroll
                for (int g = 0; g < kG; g++) {
                    S->mzred[g][warp][0] = mg[g];
                    S->mzred[g][warp][1] = zg[g];
                }
            }
        }
        __syncthreads();

        // -- finalize (m, Z) across the 16 warps --
        if (warp < kG && lane < 16) {
            float m = S->mzred[warp][lane][0];
            float z = S->mzred[warp][lane][1];
            #pragma unroll
            for (int off = 8; off; off >>= 1) {
                const float om = __shfl_xor_sync(0x0000ffffu, m, off);
                const float oz = __shfl_xor_sync(0x0000ffffu, z, off);
                const float nm = fmaxf(m, om);
                z = z * __expf(m - nm) + oz * __expf(om - nm);
                m = nm;
            }
            if (lane == 0) {
                S->scal[warp][0] = m;
                S->scal[warp][1] = 1.f / z;
            }
        }
        __syncthreads();
    }
}

extern "C" void kernel_launch(void* const* d_in, const int* in_sizes, int n_in,
                              void* d_out, int out_size) {
    const float* x = (const float*)d_in[0];            // [64, 8, 800]
    const float* W = (const float*)d_in[1];            // [128, 800, 8, 16]
    float* out = (float*)d_out;                        // [64, 16, 128]

    static_assert(sizeof(Smem) <= 113 * 1024, "need 2 CTAs/SM");
    cudaFuncSetAttribute(caps_route_kernel,
                         cudaFuncAttributeMaxDynamicSharedMemorySize,
                         (int)sizeof(Smem));
    caps_route_kernel<<<kNC * kBPC, kT, sizeof(Smem)>>>(x, W, out);
}

// round 4
// speedup vs baseline: 1.3347x; 1.0018x over previous
#include <cuda_runtime.h>
#include <cuda_fp16.h>

// CapsuleLayer dynamic routing, fused single kernel, round 3.
// x: [B=64, Cin=8, R=800] fp32
// W: [NC=128, R=800, Cin=8, O=16] fp32
// out: [B=64, O=16, NC=128] fp32
//
// R3 change: phase-2 prior rows are read with explicit LDS.128 (uint4) —
// the R2 per-__half2 loads compiled to 4x LDS.32 with a 4-way bank
// conflict (16 wavefronts/row instead of 4), which made L1tex the
// bottleneck (76.9%).

namespace {

constexpr int kB    = 64;
constexpr int kCin  = 8;
constexpr int kR    = 800;
constexpr int kNC   = 128;
constexpr int kO    = 16;
constexpr int kG    = 2;
constexpr int kT    = 512;
constexpr int kBPC  = kB / kG;        // 32 CTAs per capsule
constexpr int kIters = 3;
constexpr int kWRow = kCin * kO;      // 128 floats per W r-row

struct Smem {
    __half2 prio[kG][kR][kO / 2];     // 51200 B, row = 32B
    float   xs[kG][kCin][kR];         // 51200 B
    float   logits[kG][kR];           //  6400 B
    float   sred[kG][16][kO];         //  2048 B  (per-warp s partials)
    float   mzred[kG][16][2];         //   256 B  (per-warp online m,z)
    float   v[kG][kO];                //   128 B
    float   scal[kG][2];              //    16 B  (m, 1/Z)
};

union RowCv { uint4 u; __half2 h[4]; };

} // namespace

__global__ __launch_bounds__(kT, 2)
void caps_route_kernel(const float* __restrict__ x,
                       const float* __restrict__ W,
                       float* __restrict__ out) {
    extern __shared__ char smem_raw[];
    Smem* S = reinterpret_cast<Smem*>(smem_raw);

    const int t    = threadIdx.x;
    const int lane = t & 31;
    const int warp = t >> 5;
    const int c    = blockIdx.x / kBPC;
    const int b0   = (blockIdx.x % kBPC) * kG;
    const float* Wc = W + (size_t)c * (kR * kWRow);

    // ---- stage x slices (fp32) ----
    #pragma unroll
    for (int g = 0; g < kG; g++) {
        const float4* src = reinterpret_cast<const float4*>(x + (size_t)(b0 + g) * (kCin * kR));
        float4* dst = reinterpret_cast<float4*>(&S->xs[g][0][0]);
        for (int i = t; i < (kCin * kR) / 4; i += kT) dst[i] = src[i];
    }
    __syncthreads();

    // ---- phase 1: priors[g][r][o] = sum_i x[g][i][r] * W[c,r,i,o] ----
    // lane = (rr:2 | lo3:3). Each LDG.128 covers 4 whole 128B lines.
    {
        const int lo3   = lane & 7;
        const int rr    = lane >> 3;
        const int ihalf = lo3 >> 2;
        const int oq    = lo3 & 3;
        for (int gi = warp; gi < kR / 4; gi += kT / 32) {
            const int r = gi * 4 + rr;
            float xv0[4], xv1[4];
            #pragma unroll
            for (int k = 0; k < 4; k++) {
                xv0[k] = S->xs[0][2 * k + ihalf][r];
                xv1[k] = S->xs[1][2 * k + ihalf][r];
            }
            const float4* wr = reinterpret_cast<const float4*>(Wc + (size_t)r * kWRow) + lo3;
            float4 a0 = make_float4(0.f, 0.f, 0.f, 0.f);
            float4 a1 = make_float4(0.f, 0.f, 0.f, 0.f);
            #pragma unroll
            for (int ch = 0; ch < 4; ch++) {
                const float4 w = __ldg(wr + ch * 8);   // +128B per chunk
                a0.x = fmaf(w.x, xv0[ch], a0.x);
                a0.y = fmaf(w.y, xv0[ch], a0.y);
                a0.z = fmaf(w.z, xv0[ch], a0.z);
                a0.w = fmaf(w.w, xv0[ch], a0.w);
                a1.x = fmaf(w.x, xv1[ch], a1.x);
                a1.y = fmaf(w.y, xv1[ch], a1.y);
                a1.z = fmaf(w.z, xv1[ch], a1.z);
                a1.w = fmaf(w.w, xv1[ch], a1.w);
            }
            // combine the two i-halves (partner = lane ^ 4)
            a0.x += __shfl_xor_sync(0xffffffffu, a0.x, 4);
            a0.y += __shfl_xor_sync(0xffffffffu, a0.y, 4);
            a0.z += __shfl_xor_sync(0xffffffffu, a0.z, 4);
            a0.w += __shfl_xor_sync(0xffffffffu, a0.w, 4);
            a1.x += __shfl_xor_sync(0xffffffffu, a1.x, 4);
            a1.y += __shfl_xor_sync(0xffffffffu, a1.y, 4);
            a1.z += __shfl_xor_sync(0xffffffffu, a1.z, 4);
            a1.w += __shfl_xor_sync(0xffffffffu, a1.w, 4);
            if (ihalf == 0) {
                union { __half2 h[2]; uint2 u; } cv;
                cv.h[0] = __floats2half2_rn(a0.x, a0.y);
                cv.h[1] = __floats2half2_rn(a0.z, a0.w);
                *reinterpret_cast<uint2*>(&S->prio[0][r][oq * 2]) = cv.u;
                cv.h[0] = __floats2half2_rn(a1.x, a1.y);
                cv.h[1] = __floats2half2_rn(a1.z, a1.w);
                *reinterpret_cast<uint2*>(&S->prio[1][r][oq * 2]) = cv.u;
            }
        }
    }
    __syncthreads();

    // ---- phase 2: routing ----
    // thread = (r-slot: t>>1, o-half: t&1). Row reads are explicit LDS.128.
    const int ho = t & 1;

    for (int it = 0; it < kIters; it++) {
        // -- pass A: s[g][o] = sum_r probs[g][r] * prio[g][r][o] --
        {
            float sa[kG][8];
            #pragma unroll
            for (int g = 0; g < kG; g++)
                #pragma unroll
                for (int j = 0; j < 8; j++) sa[g][j] = 0.f;

            float m0 = 0.f, iz0 = 0.f, m1 = 0.f, iz1 = 0.f;
            if (it > 0) {
                m0 = S->scal[0][0]; iz0 = S->scal[0][1];
                m1 = S->scal[1][0]; iz1 = S->scal[1][1];
            }
            for (int r = t >> 1; r < kR; r += kT / 2) {
                #pragma unroll
                for (int g = 0; g < kG; g++) {
                    float wgt;
                    if (it == 0) wgt = 1.f / kR;
                    else {
                        const float m  = (g == 0) ? m0 : m1;
                        const float iz = (g == 0) ? iz0 : iz1;
                        wgt = __expf(S->logits[g][r] - m) * iz;
                    }
                    RowCv cv;
                    cv.u = *reinterpret_cast<const uint4*>(&S->prio[g][r][ho * 4]);
                    #pragma unroll
                    for (int j = 0; j < 4; j++) {
                        const float2 p = __half22float2(cv.h[j]);
                        sa[g][2 * j]     = fmaf(wgt, p.x, sa[g][2 * j]);
                        sa[g][2 * j + 1] = fmaf(wgt, p.y, sa[g][2 * j + 1]);
                    }
                }
            }
            // reduce over lanes with equal parity (strides 16,8,4,2)
            #pragma unroll
            for (int s = 16; s >= 2; s >>= 1) {
                #pragma unroll
                for (int g = 0; g < kG; g++)
                    #pragma unroll
                    for (int j = 0; j < 8; j++)
                        sa[g][j] += __shfl_xor_sync(0xffffffffu, sa[g][j], s);
            }
            if (lane < 2) {
                #pragma unroll
                for (int g = 0; g < kG; g++)
                    #pragma unroll
                    for (int j = 0; j < 8; j++)
                        S->sred[g][warp][lane * 8 + j] = sa[g][j];
            }
        }
        __syncthreads();

        // -- finalize s, squash; last iteration writes output --
        if (warp < kG && lane < 16) {
            float s = 0.f;
            #pragma unroll
            for (int w = 0; w < 16; w++) s += S->sred[warp][w][lane];
            float sq = s * s;
            #pragma unroll
            for (int off = 8; off; off >>= 1)
                sq += __shfl_xor_sync(0x0000ffffu, sq, off);
            const float coef = sqrtf(sq) / (1.f + sq);
            const float vv = s * coef;
            if (it < kIters - 1) S->v[warp][lane] = vv;
            else out[(size_t)(b0 + warp) * (kO * kNC) + (size_t)lane * kNC + c] = vv;
        }
        if (it == kIters - 1) return;
        __syncthreads();

        // -- pass B: delta + logits update + online (m, z) per g --
        {
            float vv[kG][8];
            #pragma unroll
            for (int g = 0; g < kG; g++)
                #pragma unroll
                for (int j = 0; j < 8; j++) vv[g][j] = S->v[g][ho * 8 + j];

            float mg[kG], zg[kG];
            #pragma unroll
            for (int g = 0; g < kG; g++) { mg[g] = -1e30f; zg[g] = 0.f; }

            for (int r = t >> 1; r < kR; r += kT / 2) {
                #pragma unroll
                for (int g = 0; g < kG; g++) {
                    RowCv cv;
                    cv.u = *reinterpret_cast<const uint4*>(&S->prio[g][r][ho * 4]);
                    float dh = 0.f;
                    #pragma unroll
                    for (int j = 0; j < 4; j++) {
                        const float2 p = __half22float2(cv.h[j]);
                        dh = fmaf(p.x, vv[g][2 * j], dh);
                        dh = fmaf(p.y, vv[g][2 * j + 1], dh);
                    }
                    const float d = dh + __shfl_xor_sync(0xffffffffu, dh, 1);
                    if (ho == 0) {
                        const float lg = (it == 0 ? 0.f : S->logits[g][r]) + d;
                        S->logits[g][r] = lg;
                        const float nm = fmaxf(mg[g], lg);
                        zg[g] = zg[g] * __expf(mg[g] - nm) + __expf(lg - nm);
                        mg[g] = nm;
                    }
                }
            }
            // warp-level online merge (odd lanes are neutral: m=-1e30, z=0)
            #pragma unroll
            for (int s = 16; s >= 1; s >>= 1) {
                #pragma unroll
                for (int g = 0; g < kG; g++) {
                    const float om = __shfl_xor_sync(0xffffffffu, mg[g], s);
                    const float oz = __shfl_xor_sync(0xffffffffu, zg[g], s);
                    const float nm = fmaxf(mg[g], om);
                    zg[g] = zg[g] * __expf(mg[g] - nm) + oz * __expf(om - nm);
                    mg[g] = nm;
                }
            }
            if (lane == 0) {
                #pragma unroll
                for (int g = 0; g < kG; g++) {
                    S->mzred[g][warp][0] = mg[g];
                    S->mzred[g][warp][1] = zg[g];
                }
            }
        }
        __syncthreads();

        // -- finalize (m, Z) across the 16 warps --
        if (warp < kG && lane < 16) {
            float m = S->mzred[warp][lane][0];
            float z = S->mzred[warp][lane][1];
            #pragma unroll
            for (int off = 8; off; off >>= 1) {
                const float om = __shfl_xor_sync(0x0000ffffu, m, off);
                const float oz = __shfl_xor_sync(0x0000ffffu, z, off);
                const float nm = fmaxf(m, om);
                z = z * __expf(m - nm) + oz * __expf(om - nm);
                m = nm;
            }
            if (lane == 0) {
                S->scal[warp][0] = m;
                S->scal[warp][1] = 1.f / z;
            }
        }
        __syncthreads();
    }
}

extern "C" void kernel_launch(void* const* d_in, const int* in_sizes, int n_in,
                              void* d_out, int out_size) {
    const float* x = (const float*)d_in[0];            // [64, 8, 800]
    const float* W = (const float*)d_in[1];            // [128, 800, 8, 16]
    float* out = (float*)d_out;                        // [64, 16, 128]

    static_assert(sizeof(Smem) <= 113 * 1024, "need 2 CTAs/SM");
    cudaFuncSetAttribute(caps_route_kernel,
                         cudaFuncAttributeMaxDynamicSharedMemorySize,
                         (int)sizeof(Smem));
    caps_route_kernel<<<kNC * kBPC, kT, sizeof(Smem)>>>(x, W, out);
}

// round 5
// speedup vs baseline: 1.5218x; 1.1402x over previous
#include <cuda_runtime.h>
#include <cuda_fp16.h>

// CapsuleLayer dynamic routing, fused single kernel, round 4.
// x: [B=64, Cin=8, R=800] fp32 ; W: [NC=128, R=800, Cin=8, O=16] fp32
// out: [B=64, O=16, NC=128] fp32
//
// R4: (1) xs rows padded to 808 -> conflict-free phase-1 x broadcast loads.
//     (2) iteration-0 s-sum fused into phase 1 (priors summed in registers).
//     (3) logit-update and next softmax-weighted sum fused into ONE pass
//         over priors using online (m,z) rescaling  -> 2 prior passes total.

namespace {

constexpr int kB    = 64;
constexpr int kCin  = 8;
constexpr int kR    = 800;
constexpr int kNC   = 128;
constexpr int kO    = 16;
constexpr int kG    = 2;
constexpr int kT    = 512;
constexpr int kBPC  = kB / kG;
constexpr int kWRow = kCin * kO;
constexpr int kXPad = kR + 8;         // 808: i-stride = 8 mod 32 banks

struct Smem {
    __half2 prio[kG][kR][kO / 2];     // 51200 B
    float   xs[kG][kCin][kXPad];      // 51712 B
    float   logits[kG][kR];           //  6400 B
    float   sred[kG][16][kO];         //  2048 B
    float   mz[kG][16][2];            //   256 B
    float   esc[kG][16];              //   128 B
    float   v[kG][kO];                //   128 B
};

union RowCv { uint4 u; __half2 h[4]; };

__device__ __forceinline__ void squash_write(Smem* S, int g, int lane, float s,
                                             bool last, float* out, int b0, int c) {
    float sq = s * s;
    #pragma unroll
    for (int off = 8; off; off >>= 1)
        sq += __shfl_xor_sync(0x0000ffffu, sq, off);
    const float coef = sqrtf(sq) / (1.f + sq);
    const float vv = s * coef;
    if (!last) S->v[g][lane] = vv;
    else out[(size_t)(b0 + g) * (kO * kNC) + (size_t)lane * kNC + c] = vv;
}

} // namespace

__global__ __launch_bounds__(kT, 2)
void caps_route_kernel(const float* __restrict__ x,
                       const float* __restrict__ W,
                       float* __restrict__ out) {
    extern __shared__ char smem_raw[];
    Smem* S = reinterpret_cast<Smem*>(smem_raw);

    const int t    = threadIdx.x;
    const int lane = t & 31;
    const int warp = t >> 5;
    const int c    = blockIdx.x / kBPC;
    const int b0   = (blockIdx.x % kBPC) * kG;
    const float* Wc = W + (size_t)c * (kR * kWRow);

    // ---- stage x slices (fp32, rows padded) ----
    #pragma unroll
    for (int g = 0; g < kG; g++) {
        const float* src = x + (size_t)(b0 + g) * (kCin * kR);
        for (int i = t; i < kCin * kR; i += kT) {
            const int ci = i / kR, r = i - ci * kR;
            S->xs[g][ci][r] = src[i];
        }
    }
    __syncthreads();

    // ---- phase 1: priors + fused uniform s-sum ----
    // lane = (rr:2 | ihalf:1 | oq:2). Each LDG.128 covers 4 whole 128B lines.
    {
        const int lo3   = lane & 7;
        const int rr    = lane >> 3;
        const int ihalf = lo3 >> 2;
        const int oq    = lo3 & 3;
        float ss0[4] = {0.f, 0.f, 0.f, 0.f};
        float ss1[4] = {0.f, 0.f, 0.f, 0.f};

        for (int gi = warp; gi < kR / 4; gi += kT / 32) {
            const int r = gi * 4 + rr;
            float xv0[4], xv1[4];
            #pragma unroll
            for (int k = 0; k < 4; k++) {
                xv0[k] = S->xs[0][2 * k + ihalf][r];
                xv1[k] = S->xs[1][2 * k + ihalf][r];
            }
            const float4* wr = reinterpret_cast<const float4*>(Wc + (size_t)r * kWRow) + lo3;
            float4 a0 = make_float4(0.f, 0.f, 0.f, 0.f);
            float4 a1 = make_float4(0.f, 0.f, 0.f, 0.f);
            #pragma unroll
            for (int ch = 0; ch < 4; ch++) {
                const float4 w = __ldg(wr + ch * 8);
                a0.x = fmaf(w.x, xv0[ch], a0.x);
                a0.y = fmaf(w.y, xv0[ch], a0.y);
                a0.z = fmaf(w.z, xv0[ch], a0.z);
                a0.w = fmaf(w.w, xv0[ch], a0.w);
                a1.x = fmaf(w.x, xv1[ch], a1.x);
                a1.y = fmaf(w.y, xv1[ch], a1.y);
                a1.z = fmaf(w.z, xv1[ch], a1.z);
                a1.w = fmaf(w.w, xv1[ch], a1.w);
            }
            a0.x += __shfl_xor_sync(0xffffffffu, a0.x, 4);
            a0.y += __shfl_xor_sync(0xffffffffu, a0.y, 4);
            a0.z += __shfl_xor_sync(0xffffffffu, a0.z, 4);
            a0.w += __shfl_xor_sync(0xffffffffu, a0.w, 4);
            a1.x += __shfl_xor_sync(0xffffffffu, a1.x, 4);
            a1.y += __shfl_xor_sync(0xffffffffu, a1.y, 4);
            a1.z += __shfl_xor_sync(0xffffffffu, a1.z, 4);
            a1.w += __shfl_xor_sync(0xffffffffu, a1.w, 4);
            if (ihalf == 0) {
                union { __half2 h[2]; uint2 u; } cv;
                cv.h[0] = __floats2half2_rn(a0.x, a0.y);
                cv.h[1] = __floats2half2_rn(a0.z, a0.w);
                *reinterpret_cast<uint2*>(&S->prio[0][r][oq * 2]) = cv.u;
                cv.h[0] = __floats2half2_rn(a1.x, a1.y);
                cv.h[1] = __floats2half2_rn(a1.z, a1.w);
                *reinterpret_cast<uint2*>(&S->prio[1][r][oq * 2]) = cv.u;
                ss0[0] += a0.x; ss0[1] += a0.y; ss0[2] += a0.z; ss0[3] += a0.w;
                ss1[0] += a1.x; ss1[1] += a1.y; ss1[2] += a1.z; ss1[3] += a1.w;
            }
        }
        // reduce over rr (lane bits 3,4); ihalf==1 lanes hold zeros
        #pragma unroll
        for (int s = 16; s >= 8; s >>= 1) {
            #pragma unroll
            for (int j = 0; j < 4; j++) {
                ss0[j] += __shfl_xor_sync(0xffffffffu, ss0[j], s);
                ss1[j] += __shfl_xor_sync(0xffffffffu, ss1[j], s);
            }
        }
        if (lane < 4) {
            #pragma unroll
            for (int j = 0; j < 4; j++) {
                S->sred[0][warp][lane * 4 + j] = ss0[j];
                S->sred[1][warp][lane * 4 + j] = ss1[j];
            }
        }
    }
    __syncthreads();

    // ---- it=0 finalize: s = (1/R) * sum, squash -> v0 ----
    if (warp < kG && lane < 16) {
        float s = 0.f;
        #pragma unroll
        for (int w = 0; w < 16; w++) s += S->sred[warp][w][lane];
        squash_write(S, warp, lane, s * (1.f / kR), false, out, b0, c);
    }
    __syncthreads();

    // ---- fused passes: delta -> logits -> online softmax-weighted sum ----
    const int ho = t & 1;

    #pragma unroll
    for (int pass = 0; pass < 2; pass++) {
        const bool first = (pass == 0);
        const bool last  = (pass == 1);

        float vv[kG][8];
        #pragma unroll
        for (int g = 0; g < kG; g++)
            #pragma unroll
            for (int j = 0; j < 8; j++) vv[g][j] = S->v[g][ho * 8 + j];

        float m[kG], z[kG], sa[kG][8];
        #pragma unroll
        for (int g = 0; g < kG; g++) {
            m[g] = -1e30f; z[g] = 0.f;
            #pragma unroll
            for (int j = 0; j < 8; j++) sa[g][j] = 0.f;
        }

        for (int r = t >> 1; r < kR; r += kT / 2) {
            #pragma unroll
            for (int g = 0; g < kG; g++) {
                RowCv cv;
                cv.u = *reinterpret_cast<const uint4*>(&S->prio[g][r][ho * 4]);
                float p[8];
                #pragma unroll
                for (int j = 0; j < 4; j++) {
                    const float2 pf = __half22float2(cv.h[j]);
                    p[2 * j] = pf.x; p[2 * j + 1] = pf.y;
                }
                float dh = 0.f;
                #pragma unroll
                for (int j = 0; j < 8; j++) dh = fmaf(p[j], vv[g][j], dh);
                const float d  = dh + __shfl_xor_sync(0xffffffffu, dh, 1);
                const float lg = (first ? 0.f : S->logits[g][r]) + d;
                if (!last && ho == 0) S->logits[g][r] = lg;
                const float nm = fmaxf(m[g], lg);
                const float f  = __expf(m[g] - nm);
                const float e  = __expf(lg - nm);
                z[g] = z[g] * f + e;
                #pragma unroll
                for (int j = 0; j < 8; j++) sa[g][j] = sa[g][j] * f + e * p[j];
                m[g] = nm;
            }
        }
        // in-warp merge over same-parity lanes (strides 16,8,4,2)
        #pragma unroll
        for (int s = 16; s >= 2; s >>= 1) {
            #pragma unroll
            for (int g = 0; g < kG; g++) {
                const float om = __shfl_xor_sync(0xffffffffu, m[g], s);
                const float oz = __shfl_xor_sync(0xffffffffu, z[g], s);
                float osa[8];
                #pragma unroll
                for (int j = 0; j < 8; j++)
                    osa[j] = __shfl_xor_sync(0xffffffffu, sa[g][j], s);
                const float nm = fmaxf(m[g], om);
                const float f1 = __expf(m[g] - nm);
                const float f2 = __expf(om - nm);
                z[g] = z[g] * f1 + oz * f2;
                #pragma unroll
                for (int j = 0; j < 8; j++) sa[g][j] = sa[g][j] * f1 + osa[j] * f2;
                m[g] = nm;
            }
        }
        if (lane < 2) {
            #pragma unroll
            for (int g = 0; g < kG; g++) {
                if (lane == 0) { S->mz[g][warp][0] = m[g]; S->mz[g][warp][1] = z[g]; }
                #pragma unroll
                for (int j = 0; j < 8; j++)
                    S->sred[g][warp][lane * 8 + j] = sa[g][j];
            }
        }
        __syncthreads();

        // cross-warp merge + squash (one warp per g)
        if (warp < kG && lane < 16) {
            const int g = warp;
            const float ml = S->mz[g][lane][0];
            const float zl = S->mz[g][lane][1];
            float M = ml;
            #pragma unroll
            for (int off = 8; off; off >>= 1)
                M = fmaxf(M, __shfl_xor_sync(0x0000ffffu, M, off));
            const float ev = __expf(ml - M);
            S->esc[g][lane] = ev;
            float Z = zl * ev;
            #pragma unroll
            for (int off = 8; off; off >>= 1)
                Z += __shfl_xor_sync(0x0000ffffu, Z, off);
            __syncwarp(0x0000ffffu);
            float num = 0.f;
            #pragma unroll
            for (int w = 0; w < 16; w++)
                num = fmaf(S->sred[g][w][lane], S->esc[g][w], num);
            squash_write(S, g, lane, num / Z, last, out, b0, c);
        }
        if (!last) __syncthreads();
    }
}

extern "C" void kernel_launch(void* const* d_in, const int* in_sizes, int n_in,
                              void* d_out, int out_size) {
    const float* x = (const float*)d_in[0];            // [64, 8, 800]
    const float* W = (const float*)d_in[1];            // [128, 800, 8, 16]
    float* out = (float*)d_out;                        // [64, 16, 128]

    static_assert(sizeof(Smem) <= 113 * 1024, "need 2 CTAs/SM");
    cudaFuncSetAttribute(caps_route_kernel,
                         cudaFuncAttributeMaxDynamicSharedMemorySize,
                         (int)sizeof(Smem));
    caps_route_kernel<<<kNC * kBPC, kT, sizeof(Smem)>>>(x, W, out);
}

// round 6
// speedup vs baseline: 1.6864x; 1.1081x over previous
#include <cuda_runtime.h>
#include <cuda_fp16.h>

// CapsuleLayer dynamic routing, fused single kernel, round 5.
// x: [B=64, Cin=8, R=800] fp32 ; W: [NC=128, R=800, Cin=8, O=16] fp32
// out: [B=64, O=16, NC=128] fp32
//
// R5: (1) __expf (MUFU, 0.5/cyc/SM, ~176us serialized!) replaced by an
//         FMA-pipe polynomial exp (magic-round + 2^f Taylor + bit splice).
//     (2) online max removed: logits provably bounded (|d| < ~50), plain
//         exp accumulation; merges become pure adds.
//     (3) logits array eliminated via linearity: logits_k = prio.(sum v_j),
//         pass 2 re-derives weights from vacc = v0+v1.

namespace {

constexpr int kB    = 64;
constexpr int kCin  = 8;
constexpr int kR    = 800;
constexpr int kNC   = 128;
constexpr int kO    = 16;
constexpr int kG    = 2;
constexpr int kT    = 512;
constexpr int kBPC  = kB / kG;
constexpr int kWRow = kCin * kO;
constexpr int kXPad = kR + 8;         // i-stride = 8 mod 32 banks

struct Smem {
    __half2 prio[kG][kR][kO / 2];     // 51200 B
    float   xs[kG][kCin][kXPad];      // 51712 B
    float   sred[kG][16][kO];         //  2048 B
    float   zred[kG][16];             //   128 B
    float   v[kG][kO];                //   128 B
};

union RowCv { uint4 u; __half2 h[4]; };

// exp(x) entirely on fma/alu pipes. Valid for |x| < ~88 (inputs bounded ~50).
__device__ __forceinline__ float fast_exp(float x) {
    const float t  = fmaf(x, 1.44269504f, 12582912.0f);   // round(x*log2e) in low mantissa
    const float fi = t - 12582912.0f;
    const float f  = fmaf(x, 1.44269504f, -fi);           // frac in [-0.5, 0.5]
    float p = 1.54035304e-4f;                              // 2^f = exp(f*ln2) Taylor
    p = fmaf(p, f, 1.33335581e-3f);
    p = fmaf(p, f, 9.61812911e-3f);
    p = fmaf(p, f, 5.55041087e-2f);
    p = fmaf(p, f, 2.40226507e-1f);
    p = fmaf(p, f, 6.93147182e-1f);
    p = fmaf(p, f, 1.0f);
    const int ii = __float_as_int(t) - 0x4B400000;         // exact integer n
    return __int_as_float(__float_as_int(p) + (ii << 23));
}

} // namespace

__global__ __launch_bounds__(kT, 2)
void caps_route_kernel(const float* __restrict__ x,
                       const float* __restrict__ W,
                       float* __restrict__ out) {
    extern __shared__ char smem_raw[];
    Smem* S = reinterpret_cast<Smem*>(smem_raw);

    const int t    = threadIdx.x;
    const int lane = t & 31;
    const int warp = t >> 5;
    const int c    = blockIdx.x / kBPC;
    const int b0   = (blockIdx.x % kBPC) * kG;
    const float* Wc = W + (size_t)c * (kR * kWRow);

    // ---- stage x slices (fp32, rows padded) ----
    #pragma unroll
    for (int g = 0; g < kG; g++) {
        const float* src = x + (size_t)(b0 + g) * (kCin * kR);
        for (int i = t; i < kCin * kR; i += kT) {
            const int ci = i / kR, r = i - ci * kR;
            S->xs[g][ci][r] = src[i];
        }
    }
    __syncthreads();

    // ---- phase 1: priors + fused uniform (it=0) s-sum ----
    {
        const int lo3   = lane & 7;
        const int rr    = lane >> 3;
        const int ihalf = lo3 >> 2;
        const int oq    = lo3 & 3;
        float ss0[4] = {0.f, 0.f, 0.f, 0.f};
        float ss1[4] = {0.f, 0.f, 0.f, 0.f};

        for (int gi = warp; gi < kR / 4; gi += kT / 32) {
            const int r = gi * 4 + rr;
            float xv0[4], xv1[4];
            #pragma unroll
            for (int k = 0; k < 4; k++) {
                xv0[k] = S->xs[0][2 * k + ihalf][r];
                xv1[k] = S->xs[1][2 * k + ihalf][r];
            }
            const float4* wr = reinterpret_cast<const float4*>(Wc + (size_t)r * kWRow) + lo3;
            float4 a0 = make_float4(0.f, 0.f, 0.f, 0.f);
            float4 a1 = make_float4(0.f, 0.f, 0.f, 0.f);
            #pragma unroll
            for (int ch = 0; ch < 4; ch++) {
                const float4 w = __ldg(wr + ch * 8);
                a0.x = fmaf(w.x, xv0[ch], a0.x);
                a0.y = fmaf(w.y, xv0[ch], a0.y);
                a0.z = fmaf(w.z, xv0[ch], a0.z);
                a0.w = fmaf(w.w, xv0[ch], a0.w);
                a1.x = fmaf(w.x, xv1[ch], a1.x);
                a1.y = fmaf(w.y, xv1[ch], a1.y);
                a1.z = fmaf(w.z, xv1[ch], a1.z);
                a1.w = fmaf(w.w, xv1[ch], a1.w);
            }
            a0.x += __shfl_xor_sync(0xffffffffu, a0.x, 4);
            a0.y += __shfl_xor_sync(0xffffffffu, a0.y, 4);
            a0.z += __shfl_xor_sync(0xffffffffu, a0.z, 4);
            a0.w += __shfl_xor_sync(0xffffffffu, a0.w, 4);
            a1.x += __shfl_xor_sync(0xffffffffu, a1.x, 4);
            a1.y += __shfl_xor_sync(0xffffffffu, a1.y, 4);
            a1.z += __shfl_xor_sync(0xffffffffu, a1.z, 4);
            a1.w += __shfl_xor_sync(0xffffffffu, a1.w, 4);
            if (ihalf == 0) {
                union { __half2 h[2]; uint2 u; } cv;
                cv.h[0] = __floats2half2_rn(a0.x, a0.y);
                cv.h[1] = __floats2half2_rn(a0.z, a0.w);
                *reinterpret_cast<uint2*>(&S->prio[0][r][oq * 2]) = cv.u;
                cv.h[0] = __floats2half2_rn(a1.x, a1.y);
                cv.h[1] = __floats2half2_rn(a1.z, a1.w);
                *reinterpret_cast<uint2*>(&S->prio[1][r][oq * 2]) = cv.u;
                ss0[0] += a0.x; ss0[1] += a0.y; ss0[2] += a0.z; ss0[3] += a0.w;
                ss1[0] += a1.x; ss1[1] += a1.y; ss1[2] += a1.z; ss1[3] += a1.w;
            }
        }
        #pragma unroll
        for (int s = 16; s >= 8; s >>= 1) {
            #pragma unroll
            for (int j = 0; j < 4; j++) {
                ss0[j] += __shfl_xor_sync(0xffffffffu, ss0[j], s);
                ss1[j] += __shfl_xor_sync(0xffffffffu, ss1[j], s);
            }
        }
        if (lane < 4) {
            #pragma unroll
            for (int j = 0; j < 4; j++) {
                S->sred[0][warp][lane * 4 + j] = ss0[j];
                S->sred[1][warp][lane * 4 + j] = ss1[j];
            }
        }
    }
    __syncthreads();

    // ---- it=0 finalize: v0 = squash(sum / R) ----
    if (warp < kG && lane < 16) {
        float s = 0.f;
        #pragma unroll
        for (int w = 0; w < 16; w++) s += S->sred[warp][w][lane];
        s *= (1.f / kR);
        float sq = s * s;
        #pragma unroll
        for (int off = 8; off; off >>= 1)
            sq += __shfl_xor_sync(0x0000ffffu, sq, off);
        const float coef = sqrtf(sq) / (1.f + sq);
        S->v[warp][lane] = s * coef;
    }
    __syncthreads();

    // ---- fused routing passes (no max, no stored logits) ----
    const int ho = t & 1;

    #pragma unroll
    for (int pass = 0; pass < 2; pass++) {
        const bool last = (pass == 1);

        float vv[kG][8];
        #pragma unroll
        for (int g = 0; g < kG; g++)
            #pragma unroll
            for (int j = 0; j < 8; j++) vv[g][j] = S->v[g][ho * 8 + j];

        float z[kG], sa[kG][8];
        #pragma unroll
        for (int g = 0; g < kG; g++) {
            z[g] = 0.f;
            #pragma unroll
            for (int j = 0; j < 8; j++) sa[g][j] = 0.f;
        }

        for (int r = t >> 1; r < kR; r += kT / 2) {
            #pragma unroll
            for (int g = 0; g < kG; g++) {
                RowCv cv;
                cv.u = *reinterpret_cast<const uint4*>(&S->prio[g][r][ho * 4]);
                float p[8];
                #pragma unroll
                for (int j = 0; j < 4; j++) {
                    const float2 pf = __half22float2(cv.h[j]);
                    p[2 * j] = pf.x; p[2 * j + 1] = pf.y;
                }
                float dh = 0.f;
                #pragma unroll
                for (int j = 0; j < 8; j++) dh = fmaf(p[j], vv[g][j], dh);
                const float d = dh + __shfl_xor_sync(0xffffffffu, dh, 1);
                const float e = fast_exp(d);      // logits bounded: |d| < ~50
                z[g] += e;
                #pragma unroll
                for (int j = 0; j < 8; j++) sa[g][j] = fmaf(e, p[j], sa[g][j]);
            }
        }
        // in-warp merge over same-parity lanes (plain adds)
        #pragma unroll
        for (int s = 16; s >= 2; s >>= 1) {
            #pragma unroll
            for (int g = 0; g < kG; g++) {
                z[g] += __shfl_xor_sync(0xffffffffu, z[g], s);
                #pragma unroll
                for (int j = 0; j < 8; j++)
                    sa[g][j] += __shfl_xor_sync(0xffffffffu, sa[g][j], s);
            }
        }
        if (lane < 2) {
            #pragma unroll
            for (int g = 0; g < kG; g++) {
                if (lane == 0) S->zred[g][warp] = z[g];
                #pragma unroll
                for (int j = 0; j < 8; j++)
                    S->sred[g][warp][lane * 8 + j] = sa[g][j];
            }
        }
        __syncthreads();

        // cross-warp finalize + squash (one warp per g)
        if (warp < kG && lane < 16) {
            const int g = warp;
            float Z = S->zred[g][lane];
            #pragma unroll
            for (int off = 8; off; off >>= 1)
                Z += __shfl_xor_sync(0x0000ffffu, Z, off);
            float num = 0.f;
            #pragma unroll
            for (int w = 0; w < 16; w++) num += S->sred[g][w][lane];
            const float s = num / Z;
            float sq = s * s;
            #pragma unroll
            for (int off = 8; off; off >>= 1)
                sq += __shfl_xor_sync(0x0000ffffu, sq, off);
            const float coef = sqrtf(sq) / (1.f + sq);
            const float vnew = s * coef;
            if (!last) S->v[g][lane] += vnew;   // vacc = v0 + v1 (linearity)
            else out[(size_t)(b0 + g) * (kO * kNC) + (size_t)lane * kNC + c] = vnew;
        }
        if (!last) __syncthreads();
    }
}

extern "C" void kernel_launch(void* const* d_in, const int* in_sizes, int n_in,
                              void* d_out, int out_size) {
    const float* x = (const float*)d_in[0];            // [64, 8, 800]
    const float* W = (const float*)d_in[1];            // [128, 800, 8, 16]
    float* out = (float*)d_out;                        // [64, 16, 128]

    static_assert(sizeof(Smem) <= 113 * 1024, "need 2 CTAs/SM");
    cudaFuncSetAttribute(caps_route_kernel,
                         cudaFuncAttributeMaxDynamicSharedMemorySize,
                         (int)sizeof(Smem));
    caps_route_kernel<<<kNC * kBPC, kT, sizeof(Smem)>>>(x, W, out);
}

// round 7
// speedup vs baseline: 2.1587x; 1.2801x over previous
#include <cuda_runtime.h>
#include <cuda_fp16.h>

// CapsuleLayer dynamic routing, fused single kernel, round 6.
// x: [B=64, Cin=8, R=800] fp32 ; W: [NC=128, R=800, Cin=8, O=16] fp32
// out: [B=64, O=16, NC=128] fp32
//
// R6: (1) phase-1 lane = (rr:3, oq:2): full o-quad per lane across all 8 i
//         -> no i-half shuffles, W LDGs stay line-optimal (3200 wf floor).
//     (2) x staged as fp16 16B rows -> one conflict-free LDS.128 per group.
//     (3) phase-2 g-per-warp-half -> butterfly merge cost halved.

namespace {

constexpr int kB    = 64;
constexpr int kCin  = 8;
constexpr int kR    = 800;
constexpr int kNC   = 128;
constexpr int kO    = 16;
constexpr int kG    = 2;
constexpr int kT    = 512;
constexpr int kBPC  = kB / kG;
constexpr int kWRow = kCin * kO;

struct Smem {
    __half2 prio[kG][kR][kO / 2];     // 51200 B
    __half  xsh[kG][kR][kCin];        // 25600 B (16B rows, LDS.128-friendly)
    float   sred[kG][16][kO];         //  2048 B
    float   zred[kG][8];              //    64 B
    float   v[kG][kO];                //   128 B
};

// exp(x) entirely on fma/alu pipes. Valid for |x| < ~88 (inputs bounded ~50).
__device__ __forceinline__ float fast_exp(float x) {
    const float t  = fmaf(x, 1.44269504f, 12582912.0f);
    const float fi = t - 12582912.0f;
    const float f  = fmaf(x, 1.44269504f, -fi);
    float p = 1.54035304e-4f;
    p = fmaf(p, f, 1.33335581e-3f);
    p = fmaf(p, f, 9.61812911e-3f);
    p = fmaf(p, f, 5.55041087e-2f);
    p = fmaf(p, f, 2.40226507e-1f);
    p = fmaf(p, f, 6.93147182e-1f);
    p = fmaf(p, f, 1.0f);
    const int ii = __float_as_int(t) - 0x4B400000;
    return __int_as_float(__float_as_int(p) + (ii << 23));
}

} // namespace

__global__ __launch_bounds__(kT, 2)
void caps_route_kernel(const float* __restrict__ x,
                       const float* __restrict__ W,
                       float* __restrict__ out) {
    extern __shared__ char smem_raw[];
    Smem* S = reinterpret_cast<Smem*>(smem_raw);

    const int t    = threadIdx.x;
    const int lane = t & 31;
    const int warp = t >> 5;
    const int c    = blockIdx.x / kBPC;
    const int b0   = (blockIdx.x % kBPC) * kG;
    const float* Wc = W + (size_t)c * (kR * kWRow);

    // ---- stage x as fp16 rows: xsh[g][r][i], one row = 16B ----
    for (int rowIdx = t; rowIdx < kG * kR; rowIdx += kT) {
        const int g = rowIdx >= kR;
        const int r = rowIdx - g * kR;
        const float* src = x + (size_t)(b0 + g) * (kCin * kR) + r;
        union { __half2 h[4]; uint4 u; } cv;
        #pragma unroll
        for (int k = 0; k < 4; k++)
            cv.h[k] = __floats2half2_rn(src[(2 * k) * kR], src[(2 * k + 1) * kR]);
        *reinterpret_cast<uint4*>(&S->xsh[g][r][0]) = cv.u;
    }
    __syncthreads();

    // ---- phase 1: priors + fused uniform (it=0) s-sum ----
    // lane = (rr:3 | oq:2): 8 rows x 4 o-quads per warp-iteration.
    {
        const int oq = lane & 3;
        const int rr = lane >> 2;
        float ss0[4] = {0.f, 0.f, 0.f, 0.f};
        float ss1[4] = {0.f, 0.f, 0.f, 0.f};

        for (int grp = warp; grp < kR / 8; grp += kT / 32) {
            const int r = grp * 8 + rr;
            union { uint4 u; __half2 h[4]; } xa, xb;
            xa.u = *reinterpret_cast<const uint4*>(&S->xsh[0][r][0]);
            xb.u = *reinterpret_cast<const uint4*>(&S->xsh[1][r][0]);
            float xv0[8], xv1[8];
            #pragma unroll
            for (int k = 0; k < 4; k++) {
                const float2 f0 = __half22float2(xa.h[k]);
                const float2 f1 = __half22float2(xb.h[k]);
                xv0[2 * k] = f0.x; xv0[2 * k + 1] = f0.y;
                xv1[2 * k] = f1.x; xv1[2 * k + 1] = f1.y;
            }
            const float4* wr = reinterpret_cast<const float4*>(Wc + (size_t)r * kWRow) + oq;
            float4 a0 = make_float4(0.f, 0.f, 0.f, 0.f);
            float4 a1 = make_float4(0.f, 0.f, 0.f, 0.f);
            #pragma unroll
            for (int i = 0; i < 8; i++) {
                const float4 w = __ldg(wr + i * 4);   // +64B per i
                a0.x = fmaf(w.x, xv0[i], a0.x);
                a0.y = fmaf(w.y, xv0[i], a0.y);
                a0.z = fmaf(w.z, xv0[i], a0.z);
                a0.w = fmaf(w.w, xv0[i], a0.w);
                a1.x = fmaf(w.x, xv1[i], a1.x);
                a1.y = fmaf(w.y, xv1[i], a1.y);
                a1.z = fmaf(w.z, xv1[i], a1.z);
                a1.w = fmaf(w.w, xv1[i], a1.w);
            }
            union { __half2 h[2]; uint2 u; } pv;
            pv.h[0] = __floats2half2_rn(a0.x, a0.y);
            pv.h[1] = __floats2half2_rn(a0.z, a0.w);
            *reinterpret_cast<uint2*>(&S->prio[0][r][oq * 2]) = pv.u;
            pv.h[0] = __floats2half2_rn(a1.x, a1.y);
            pv.h[1] = __floats2half2_rn(a1.z, a1.w);
            *reinterpret_cast<uint2*>(&S->prio[1][r][oq * 2]) = pv.u;
            ss0[0] += a0.x; ss0[1] += a0.y; ss0[2] += a0.z; ss0[3] += a0.w;
            ss1[0] += a1.x; ss1[1] += a1.y; ss1[2] += a1.z; ss1[3] += a1.w;
        }
        // reduce over rr (lane bits 2..4)
        #pragma unroll
        for (int s = 4; s <= 16; s <<= 1) {
            #pragma unroll
            for (int j = 0; j < 4; j++) {
                ss0[j] += __shfl_xor_sync(0xffffffffu, ss0[j], s);
                ss1[j] += __shfl_xor_sync(0xffffffffu, ss1[j], s);
            }
        }
        if (rr == 0) {
            *reinterpret_cast<float4*>(&S->sred[0][warp][oq * 4]) =
                make_float4(ss0[0], ss0[1], ss0[2], ss0[3]);
            *reinterpret_cast<float4*>(&S->sred[1][warp][oq * 4]) =
                make_float4(ss1[0], ss1[1], ss1[2], ss1[3]);
        }
    }
    __syncthreads();

    // ---- it=0 finalize: v0 = squash(sum / R) ----
    if (warp < kG && lane < 16) {
        float s = 0.f;
        #pragma unroll
        for (int w = 0; w < 16; w++) s += S->sred[warp][w][lane];
        s *= (1.f / kR);
        float sq = s * s;
        #pragma unroll
        for (int off = 8; off; off >>= 1)
            sq += __shfl_xor_sync(0x0000ffffu, sq, off);
        const float coef = sqrtf(sq) / (1.f + sq);
        S->v[warp][lane] = s * coef;
    }
    __syncthreads();

    // ---- fused routing passes: g per warp-half ----
    const int g2 = warp >> 3;             // warps 0-7: g0, 8-15: g1
    const int wl = warp & 7;
    const int ho = lane & 1;
    const int rs = wl * 16 + (lane >> 1); // 0..127, stride 128 over r

    #pragma unroll
    for (int pass = 0; pass < 2; pass++) {
        const bool last = (pass == 1);

        float vv[8];
        #pragma unroll
        for (int j = 0; j < 8; j++) vv[j] = S->v[g2][ho * 8 + j];

        float z = 0.f, sa[8];
        #pragma unroll
        for (int j = 0; j < 8; j++) sa[j] = 0.f;

        for (int r = rs; r < kR; r += 128) {
            union { uint4 u; __half2 h[4]; } cv;
            cv.u = *reinterpret_cast<const uint4*>(&S->prio[g2][r][ho * 4]);
            float p[8];
            #pragma unroll
            for (int k = 0; k < 4; k++) {
                const float2 pf = __half22float2(cv.h[k]);
                p[2 * k] = pf.x; p[2 * k + 1] = pf.y;
            }
            float dh = 0.f;
            #pragma unroll
            for (int j = 0; j < 8; j++) dh = fmaf(p[j], vv[j], dh);
            const float d = dh + __shfl_xor_sync(0xffffffffu, dh, 1);
            const float e = fast_exp(d);      // logits bounded: |d| < ~50
            z += e;
            #pragma unroll
            for (int j = 0; j < 8; j++) sa[j] = fmaf(e, p[j], sa[j]);
        }
        // butterfly over same-parity lanes
        #pragma unroll
        for (int s = 16; s >= 2; s >>= 1) {
            z += __shfl_xor_sync(0xffffffffu, z, s);
            #pragma unroll
            for (int j = 0; j < 8; j++)
                sa[j] += __shfl_xor_sync(0xffffffffu, sa[j], s);
        }
        if (lane < 2) {
            #pragma unroll
            for (int j = 0; j < 8; j++)
                S->sred[g2][wl][lane * 8 + j] = sa[j];
            if (lane == 0) S->zred[g2][wl] = z;
        }
        __syncthreads();

        // cross-warp finalize + squash (one warp per g)
        if (warp < kG && lane < 16) {
            const int g = warp;
            float Z = 0.f, num = 0.f;
            #pragma unroll
            for (int w = 0; w < 8; w++) {
                Z   += S->zred[g][w];
                num += S->sred[g][w][lane];
            }
            const float s = num / Z;
            float sq = s * s;
            #pragma unroll
            for (int off = 8; off; off >>= 1)
                sq += __shfl_xor_sync(0x0000ffffu, sq, off);
            const float coef = sqrtf(sq) / (1.f + sq);
            const float vnew = s * coef;
            if (!last) S->v[g][lane] += vnew;   // vacc = v0 + v1 (linearity)
            else out[(size_t)(b0 + g) * (kO * kNC) + (size_t)lane * kNC + c] = vnew;
        }
        if (!last) __syncthreads();
    }
}

extern "C" void kernel_launch(void* const* d_in, const int* in_sizes, int n_in,
                              void* d_out, int out_size) {
    const float* x = (const float*)d_in[0];            // [64, 8, 800]
    const float* W = (const float*)d_in[1];            // [128, 800, 8, 16]
    float* out = (float*)d_out;                        // [64, 16, 128]

    static_assert(sizeof(Smem) <= 113 * 1024, "need 2 CTAs/SM");
    cudaFuncSetAttribute(caps_route_kernel,
                         cudaFuncAttributeMaxDynamicSharedMemorySize,
                         (int)sizeof(Smem));
    caps_route_kernel<<<kNC * kBPC, kT, sizeof(Smem)>>>(x, W, out);
}

// round 8
// speedup vs baseline: 2.4855x; 1.1513x over previous
#include <cuda_runtime.h>
#include <cuda_fp16.h>

// CapsuleLayer dynamic routing, fused single kernel, round 7.
// x: [B=64, Cin=8, R=800] fp32 ; W: [NC=128, R=800, Cin=8, O=16] fp32
// out: [B=64, O=16, NC=128] fp32
//
// R7: G=2 -> G=4 batch items per CTA. Halves the number of CTAs reading
// each W[c] (the dominant L1-wavefront item), cutting chip-wide L1
// wavefronts ~42% at the cost of 1 CTA/SM (smem ~158KB).

namespace {

constexpr int kB    = 64;
constexpr int kCin  = 8;
constexpr int kR    = 800;
constexpr int kNC   = 128;
constexpr int kO    = 16;
constexpr int kG    = 4;
constexpr int kT    = 512;
constexpr int kBPC  = kB / kG;        // 16 CTAs per capsule
constexpr int kWRow = kCin * kO;

struct Smem {
    __half2 prio[kG][kR][kO / 2];     // 102400 B
    __half  xsh[kG][kR][kCin];        //  51200 B (16B rows)
    float   sred[kG][16][kO];         //   4096 B
    float   zred[kG][16];             //    256 B
    float   v[kG][kO];                //    256 B
};

// exp(x) entirely on fma/alu pipes. Valid for |x| < ~88 (inputs bounded ~50).
__device__ __forceinline__ float fast_exp(float x) {
    const float t  = fmaf(x, 1.44269504f, 12582912.0f);
    const float fi = t - 12582912.0f;
    const float f  = fmaf(x, 1.44269504f, -fi);
    float p = 1.54035304e-4f;
    p = fmaf(p, f, 1.33335581e-3f);
    p = fmaf(p, f, 9.61812911e-3f);
    p = fmaf(p, f, 5.55041087e-2f);
    p = fmaf(p, f, 2.40226507e-1f);
    p = fmaf(p, f, 6.93147182e-1f);
    p = fmaf(p, f, 1.0f);
    const int ii = __float_as_int(t) - 0x4B400000;
    return __int_as_float(__float_as_int(p) + (ii << 23));
}

} // namespace

__global__ __launch_bounds__(kT, 1)
void caps_route_kernel(const float* __restrict__ x,
                       const float* __restrict__ W,
                       float* __restrict__ out) {
    extern __shared__ char smem_raw[];
    Smem* S = reinterpret_cast<Smem*>(smem_raw);

    const int t    = threadIdx.x;
    const int lane = t & 31;
    const int warp = t >> 5;
    const int c    = blockIdx.x / kBPC;
    const int b0   = (blockIdx.x % kBPC) * kG;
    const float* Wc = W + (size_t)c * (kR * kWRow);

    // ---- stage x as fp16 rows: xsh[g][r][i], one row = 16B ----
    for (int rowIdx = t; rowIdx < kG * kR; rowIdx += kT) {
        const int g = rowIdx / kR;
        const int r = rowIdx - g * kR;
        const float* src = x + (size_t)(b0 + g) * (kCin * kR) + r;
        union { __half2 h[4]; uint4 u; } cv;
        #pragma unroll
        for (int k = 0; k < 4; k++)
            cv.h[k] = __floats2half2_rn(src[(2 * k) * kR], src[(2 * k + 1) * kR]);
        *reinterpret_cast<uint4*>(&S->xsh[g][r][0]) = cv.u;
    }
    __syncthreads();

    // ---- phase 1: priors + fused uniform (it=0) s-sum ----
    // lane = (rr:3 | oq:2): 8 rows x 4 o-quads per warp-iteration.
    {
        const int oq = lane & 3;
        const int rr = lane >> 2;
        float ss[kG][4];
        #pragma unroll
        for (int g = 0; g < kG; g++)
            #pragma unroll
            for (int j = 0; j < 4; j++) ss[g][j] = 0.f;

        for (int grp = warp; grp < kR / 8; grp += kT / 32) {
            const int r = grp * 8 + rr;
            float xv[kG][8];
            #pragma unroll
            for (int g = 0; g < kG; g++) {
                union { uint4 u; __half2 h[4]; } xa;
                xa.u = *reinterpret_cast<const uint4*>(&S->xsh[g][r][0]);
                #pragma unroll
                for (int k = 0; k < 4; k++) {
                    const float2 f = __half22float2(xa.h[k]);
                    xv[g][2 * k] = f.x; xv[g][2 * k + 1] = f.y;
                }
            }
            const float4* wr = reinterpret_cast<const float4*>(Wc + (size_t)r * kWRow) + oq;
            float4 acc[kG];
            #pragma unroll
            for (int g = 0; g < kG; g++) acc[g] = make_float4(0.f, 0.f, 0.f, 0.f);
            #pragma unroll
            for (int i = 0; i < 8; i++) {
                const float4 w = __ldg(wr + i * 4);   // +64B per i
                #pragma unroll
                for (int g = 0; g < kG; g++) {
                    acc[g].x = fmaf(w.x, xv[g][i], acc[g].x);
                    acc[g].y = fmaf(w.y, xv[g][i], acc[g].y);
                    acc[g].z = fmaf(w.z, xv[g][i], acc[g].z);
                    acc[g].w = fmaf(w.w, xv[g][i], acc[g].w);
                }
            }
            #pragma unroll
            for (int g = 0; g < kG; g++) {
                union { __half2 h[2]; uint2 u; } pv;
                pv.h[0] = __floats2half2_rn(acc[g].x, acc[g].y);
                pv.h[1] = __floats2half2_rn(acc[g].z, acc[g].w);
                *reinterpret_cast<uint2*>(&S->prio[g][r][oq * 2]) = pv.u;
                ss[g][0] += acc[g].x; ss[g][1] += acc[g].y;
                ss[g][2] += acc[g].z; ss[g][3] += acc[g].w;
            }
        }
        // reduce over rr (lane bits 2..4)
        #pragma unroll
        for (int s = 4; s <= 16; s <<= 1)
            #pragma unroll
            for (int g = 0; g < kG; g++)
                #pragma unroll
                for (int j = 0; j < 4; j++)
                    ss[g][j] += __shfl_xor_sync(0xffffffffu, ss[g][j], s);
        if (rr == 0) {
            #pragma unroll
            for (int g = 0; g < kG; g++)
                *reinterpret_cast<float4*>(&S->sred[g][warp][oq * 4]) =
                    make_float4(ss[g][0], ss[g][1], ss[g][2], ss[g][3]);
        }
    }
    __syncthreads();

    // ---- it=0 finalize: v0 = squash(sum / R), one warp per g ----
    if (warp < kG && lane < 16) {
        float s = 0.f;
        #pragma unroll
        for (int w = 0; w < 16; w++) s += S->sred[warp][w][lane];
        s *= (1.f / kR);
        float sq = s * s;
        #pragma unroll
        for (int off = 8; off; off >>= 1)
            sq += __shfl_xor_sync(0x0000ffffu, sq, off);
        const float coef = sqrtf(sq) / (1.f + sq);
        S->v[warp][lane] = s * coef;
    }
    __syncthreads();

    // ---- fused routing passes: g per warp-quarter ----
    const int g2 = warp >> 2;             // warps 0-3: g0, ... 12-15: g3
    const int wl = warp & 3;
    const int ho = lane & 1;
    const int rs = wl * 16 + (lane >> 1); // 0..63, stride 64 over r

    #pragma unroll
    for (int pass = 0; pass < 2; pass++) {
        const bool last = (pass == 1);

        float vv[8];
        #pragma unroll
        for (int j = 0; j < 8; j++) vv[j] = S->v[g2][ho * 8 + j];

        float z = 0.f, sa[8];
        #pragma unroll
        for (int j = 0; j < 8; j++) sa[j] = 0.f;

        for (int r = rs; r < kR; r += 64) {
            union { uint4 u; __half2 h[4]; } cv;
            cv.u = *reinterpret_cast<const uint4*>(&S->prio[g2][r][ho * 4]);
            float p[8];
            #pragma unroll
            for (int k = 0; k < 4; k++) {
                const float2 pf = __half22float2(cv.h[k]);
                p[2 * k] = pf.x; p[2 * k + 1] = pf.y;
            }
            float dh = 0.f;
            #pragma unroll
            for (int j = 0; j < 8; j++) dh = fmaf(p[j], vv[j], dh);
            const float d = dh + __shfl_xor_sync(0xffffffffu, dh, 1);
            const float e = fast_exp(d);      // logits bounded: |d| < ~50
            z += e;
            #pragma unroll
            for (int j = 0; j < 8; j++) sa[j] = fmaf(e, p[j], sa[j]);
        }
        // butterfly over same-parity lanes
        #pragma unroll
        for (int s = 16; s >= 2; s >>= 1) {
            z += __shfl_xor_sync(0xffffffffu, z, s);
            #pragma unroll
            for (int j = 0; j < 8; j++)
                sa[j] += __shfl_xor_sync(0xffffffffu, sa[j], s);
        }
        if (lane < 2) {
            #pragma unroll
            for (int j = 0; j < 8; j++)
                S->sred[g2][wl][lane * 8 + j] = sa[j];
            if (lane == 0) S->zred[g2][wl] = z;
        }
        __syncthreads();

        // cross-warp finalize + squash (one warp per g)
        if (warp < kG && lane < 16) {
            const int g = warp;
            float Z = 0.f, num = 0.f;
            #pragma unroll
            for (int w = 0; w < 4; w++) {
                Z   += S->zred[g][w];
                num += S->sred[g][w][lane];
            }
            const float s = num / Z;
            float sq = s * s;
            #pragma unroll
            for (int off = 8; off; off >>= 1)
                sq += __shfl_xor_sync(0x0000ffffu, sq, off);
            const float coef = sqrtf(sq) / (1.f + sq);
            const float vnew = s * coef;
            if (!last) S->v[g][lane] += vnew;   // vacc = v0 + v1 (linearity)
            else out[(size_t)(b0 + g) * (kO * kNC) + (size_t)lane * kNC + c] = vnew;
        }
        if (!last) __syncthreads();
    }
}

extern "C" void kernel_launch(void* const* d_in, const int* in_sizes, int n_in,
                              void* d_out, int out_size) {
    const float* x = (const float*)d_in[0];            // [64, 8, 800]
    const float* W = (const float*)d_in[1];            // [128, 800, 8, 16]
    float* out = (float*)d_out;                        // [64, 16, 128]

    static_assert(sizeof(Smem) <= 227 * 1024, "smem budget");
    cudaFuncSetAttribute(caps_route_kernel,
                         cudaFuncAttributeMaxDynamicSharedMemorySize,
                         (int)sizeof(Smem));
    caps_route_kernel<<<kNC * kBPC, kT, sizeof(Smem)>>>(x, W, out);
}